// round 5
// baseline (speedup 1.0000x reference)
#include <cuda_runtime.h>
#include <cstdint>

#define N_NODES 40000
#define N_EDGES 640000
#define DIM 128
#define BCAP 64          // bucket capacity per node (P(deg>64) ~ 1e-18, fallback handles it)
#define RT 64            // rows per GEMM block
#define WS_STRIDE 132    // padded W-shared row stride (floats)
#define AS_STRIDE 68     // padded A-shared row stride (floats)

// Scratch (no cudaMalloc allowed)
__device__ float g_agg[N_NODES * DIM];
__device__ float g_h[N_NODES * DIM];
__device__ float g_colsum[DIM];
__device__ float g_colsumsq[DIM];
__device__ int   g_cnt[N_NODES];
__device__ int   g_bucket[(size_t)N_NODES * BCAP];   // 10.24 MB

// ---------------------------------------------------------------------------
// K0: zero g_agg (needed only for the rare overflow-RED path), cnt, BN stats
// ---------------------------------------------------------------------------
__global__ void k0z() {
    const int total = N_NODES * DIM / 4;
    float4 z = {0.f, 0.f, 0.f, 0.f};
    for (int idx = blockIdx.x * blockDim.x + threadIdx.x; idx < total;
         idx += gridDim.x * blockDim.x)
        ((float4*)g_agg)[idx] = z;
    for (int idx = blockIdx.x * blockDim.x + threadIdx.x; idx < N_NODES;
         idx += gridDim.x * blockDim.x)
        g_cnt[idx] = 0;
    if (blockIdx.x == 0 && threadIdx.x < DIM) {
        g_colsum[threadIdx.x]   = 0.0f;
        g_colsumsq[threadIdx.x] = 0.0f;
    }
}

// ---------------------------------------------------------------------------
// K1a: bin edges by destination. One thread per edge.
// ---------------------------------------------------------------------------
__global__ void k1a_fill(const float* __restrict__ x, const int* __restrict__ ei) {
    int e = blockIdx.x * blockDim.x + threadIdx.x;
    if (e >= N_EDGES) return;
    int src = __ldg(&ei[e]);
    int dst = __ldg(&ei[N_EDGES + e]);
    int pos = atomicAdd(&g_cnt[dst], 1);
    if (pos < BCAP) {
        g_bucket[(size_t)dst * BCAP + pos] = src;
    } else {
        // essentially-never fallback: direct reduction of the whole row
        const float4* xr = (const float4*)x + (size_t)src * (DIM / 4);
        float* dp = g_agg + (size_t)dst * DIM;
#pragma unroll 4
        for (int q = 0; q < DIM / 4; q++) {
            float4 v = __ldg(xr + q);
            asm volatile("red.global.add.v4.f32 [%0], {%1, %2, %3, %4};"
                         :: "l"(dp + 4 * q), "f"(v.x), "f"(v.y), "f"(v.z), "f"(v.w)
                         : "memory");
        }
    }
}

// ---------------------------------------------------------------------------
// K1b: pull phase. One warp per node: gather neighbor rows, register-accumulate,
//      single plain store (RED only if the node overflowed its bucket).
// ---------------------------------------------------------------------------
__global__ void k1b_pull(const float* __restrict__ x) {
    int node = (blockIdx.x * blockDim.x + threadIdx.x) >> 5;
    int lane = threadIdx.x & 31;
    if (node >= N_NODES) return;
    int draw = g_cnt[node];
    int d = min(draw, BCAP);
    const int* bk = g_bucket + (size_t)node * BCAP;
    const float4* xv = (const float4*)x;

    float4 a = {0.f, 0.f, 0.f, 0.f};
    int j = 0;
    for (; j + 4 <= d; j += 4) {
        int4 s4 = *(const int4*)(bk + j);   // uniform across the warp
        float4 v0 = __ldg(xv + (size_t)s4.x * 32 + lane);
        float4 v1 = __ldg(xv + (size_t)s4.y * 32 + lane);
        float4 v2 = __ldg(xv + (size_t)s4.z * 32 + lane);
        float4 v3 = __ldg(xv + (size_t)s4.w * 32 + lane);
        a.x += (v0.x + v1.x) + (v2.x + v3.x);
        a.y += (v0.y + v1.y) + (v2.y + v3.y);
        a.z += (v0.z + v1.z) + (v2.z + v3.z);
        a.w += (v0.w + v1.w) + (v2.w + v3.w);
    }
    for (; j < d; j++) {
        int s = bk[j];
        float4 v = __ldg(xv + (size_t)s * 32 + lane);
        a.x += v.x; a.y += v.y; a.z += v.z; a.w += v.w;
    }

    float* dp = g_agg + (size_t)node * DIM + lane * 4;
    if (draw <= BCAP) {
        *(float4*)dp = a;   // plain store: no atomics on the hot path
    } else {
        asm volatile("red.global.add.v4.f32 [%0], {%1, %2, %3, %4};"
                     :: "l"(dp), "f"(a.x), "f"(a.y), "f"(a.z), "f"(a.w)
                     : "memory");
    }
}

// ---------------------------------------------------------------------------
// K2: h = ((1+eps)x + agg) @ W^T, fused per-column sum/sumsq for BN.
//     Bias omitted: cancels exactly inside BatchNorm. (unchanged from R3)
// ---------------------------------------------------------------------------
extern __shared__ float k2_smem[];

__global__ void __launch_bounds__(256, 2)
k2_gemm(const float* __restrict__ x, const float* __restrict__ Wm,
        const float* __restrict__ gin_eps) {
    float* Ws = k2_smem;                       // [DIM][WS_STRIDE] : Ws[k][n] = W[n][k]
    float* As = k2_smem + DIM * WS_STRIDE;     // [DIM][AS_STRIDE] : As[k][r] = A[row0+r][k]
    __shared__ float cs[DIM];
    __shared__ float cs2[DIM];

    const int tid = threadIdx.x;
    const int row0 = blockIdx.x * RT;
    const float ce = 1.0f + __ldg(gin_eps);

    for (int i = tid; i < DIM * DIM / 4; i += 256) {
        int n  = i >> 5;
        int k0 = (i & 31) << 2;
        float4 w = __ldg((const float4*)Wm + i);
        Ws[(k0 + 0) * WS_STRIDE + n] = w.x;
        Ws[(k0 + 1) * WS_STRIDE + n] = w.y;
        Ws[(k0 + 2) * WS_STRIDE + n] = w.z;
        Ws[(k0 + 3) * WS_STRIDE + n] = w.w;
    }
    for (int i = tid; i < RT * DIM / 4; i += 256) {
        int r  = i >> 5;
        int k0 = (i & 31) << 2;
        size_t off = (size_t)(row0 + r) * (DIM / 4) + (k0 >> 2);
        float4 xv = __ldg((const float4*)x + off);
        float4 gv = *((const float4*)g_agg + off);
        float4 a;
        a.x = fmaf(ce, xv.x, gv.x);
        a.y = fmaf(ce, xv.y, gv.y);
        a.z = fmaf(ce, xv.z, gv.z);
        a.w = fmaf(ce, xv.w, gv.w);
        As[(k0 + 0) * AS_STRIDE + r] = a.x;
        As[(k0 + 1) * AS_STRIDE + r] = a.y;
        As[(k0 + 2) * AS_STRIDE + r] = a.z;
        As[(k0 + 3) * AS_STRIDE + r] = a.w;
    }
    if (tid < DIM) { cs[tid] = 0.0f; cs2[tid] = 0.0f; }
    __syncthreads();

    const int cg = tid & 15;
    const int rg = tid >> 4;

    float acc[4][8];
#pragma unroll
    for (int r = 0; r < 4; r++)
#pragma unroll
        for (int c = 0; c < 8; c++) acc[r][c] = 0.0f;

#pragma unroll 4
    for (int k = 0; k < DIM; k++) {
        float4 w0 = *(float4*)&Ws[k * WS_STRIDE + cg * 8];
        float4 w1 = *(float4*)&Ws[k * WS_STRIDE + cg * 8 + 4];
        float4 av = *(float4*)&As[k * AS_STRIDE + rg * 4];
        float a[4] = {av.x, av.y, av.z, av.w};
        float w[8] = {w0.x, w0.y, w0.z, w0.w, w1.x, w1.y, w1.z, w1.w};
#pragma unroll
        for (int r = 0; r < 4; r++)
#pragma unroll
            for (int c = 0; c < 8; c++) acc[r][c] = fmaf(a[r], w[c], acc[r][c]);
    }

    float csum[8], csq[8];
#pragma unroll
    for (int c = 0; c < 8; c++) { csum[c] = 0.0f; csq[c] = 0.0f; }

#pragma unroll
    for (int r = 0; r < 4; r++) {
        int row = row0 + rg * 4 + r;
        float v[8];
#pragma unroll
        for (int c = 0; c < 8; c++) {
            v[c] = acc[r][c];
            csum[c] += v[c];
            csq[c]  += v[c] * v[c];
        }
        float4 o0 = {v[0], v[1], v[2], v[3]};
        float4 o1 = {v[4], v[5], v[6], v[7]};
        *(float4*)&g_h[(size_t)row * DIM + cg * 8]     = o0;
        *(float4*)&g_h[(size_t)row * DIM + cg * 8 + 4] = o1;
    }

#pragma unroll
    for (int c = 0; c < 8; c++) {
        atomicAdd(&cs[cg * 8 + c],  csum[c]);
        atomicAdd(&cs2[cg * 8 + c], csq[c]);
    }
    __syncthreads();
    if (tid < DIM) {
        atomicAdd(&g_colsum[tid],   cs[tid]);
        atomicAdd(&g_colsumsq[tid], cs2[tid]);
    }
}

// ---------------------------------------------------------------------------
// K3: out = relu(gamma*(h-mean)*rsqrt(var+eps)+beta) + x  (unchanged from R3)
// ---------------------------------------------------------------------------
__global__ void k3_final(const float* __restrict__ x,
                         const float* __restrict__ gamma,
                         const float* __restrict__ beta,
                         float* __restrict__ out) {
    __shared__ float sc_s[DIM], sh_s[DIM];
    if (threadIdx.x < DIM) {
        int c = threadIdx.x;
        const float invN = 1.0f / (float)N_NODES;
        float mean = g_colsum[c] * invN;
        float var  = g_colsumsq[c] * invN - mean * mean;
        float inv  = rsqrtf(var + 1e-5f);
        float sc   = __ldg(&gamma[c]) * inv;
        sc_s[c] = sc;
        sh_s[c] = __ldg(&beta[c]) - mean * sc;
    }
    __syncthreads();
    const int total = N_NODES * DIM / 4;
    for (int idx = blockIdx.x * blockDim.x + threadIdx.x; idx < total;
         idx += gridDim.x * blockDim.x) {
        int c4 = (idx & 31) << 2;
        float4 h  = ((const float4*)g_h)[idx];
        float4 xv = __ldg((const float4*)x + idx);
        float4 sc = *(float4*)&sc_s[c4];
        float4 sh = *(float4*)&sh_s[c4];
        float4 o;
        o.x = fmaxf(fmaf(h.x, sc.x, sh.x), 0.0f) + xv.x;
        o.y = fmaxf(fmaf(h.y, sc.y, sh.y), 0.0f) + xv.y;
        o.z = fmaxf(fmaf(h.z, sc.z, sh.z), 0.0f) + xv.z;
        o.w = fmaxf(fmaf(h.w, sc.w, sh.w), 0.0f) + xv.w;
        ((float4*)out)[idx] = o;
    }
}

// ---------------------------------------------------------------------------
extern "C" void kernel_launch(void* const* d_in, const int* in_sizes, int n_in,
                              void* d_out, int out_size) {
    const float* x       = (const float*)d_in[0];
    const int*   ei      = (const int*)d_in[1];
    const float* Wm      = (const float*)d_in[2];
    // d_in[3] = bias: cancels exactly inside BatchNorm -> unused
    const float* gamma   = (const float*)d_in[4];
    const float* beta    = (const float*)d_in[5];
    const float* gin_eps = (const float*)d_in[6];
    float* out = (float*)d_out;

    const int smem_k2 = (DIM * WS_STRIDE + DIM * AS_STRIDE) * sizeof(float);
    cudaFuncSetAttribute(k2_gemm, cudaFuncAttributeMaxDynamicSharedMemorySize, smem_k2);

    k0z<<<1184, 256>>>();
    k1a_fill<<<(N_EDGES + 255) / 256, 256>>>(x, ei);
    k1b_pull<<<(N_NODES * 32 + 255) / 256, 256>>>(x);
    k2_gemm<<<N_NODES / RT, 256, smem_k2>>>(x, Wm, gin_eps);
    k3_final<<<1184, 256>>>(x, gamma, beta, out);
}

// round 6
// speedup vs baseline: 1.7585x; 1.7585x over previous
#include <cuda_runtime.h>
#include <cstdint>

#define N_NODES 40000
#define N_EDGES 640000
#define DIM 128
#define KC 32            // K chunk staged in smem
#define AST 68           // As row stride (words): 64 + 4 pad
#define WST 132          // Ws row stride (words): 128 + 4 pad

// Scratch (no cudaMalloc allowed)
__device__ float g_agg[N_NODES * DIM];
__device__ float g_h[N_NODES * DIM];
__device__ float g_colsum[DIM];
__device__ float g_colsumsq[DIM];

// ---------------------------------------------------------------------------
// K0: zero g_agg + BN stat accumulators
// ---------------------------------------------------------------------------
__global__ void k0z() {
    const int total = N_NODES * DIM / 4;
    float4 z = {0.f, 0.f, 0.f, 0.f};
    for (int idx = blockIdx.x * blockDim.x + threadIdx.x; idx < total;
         idx += gridDim.x * blockDim.x)
        ((float4*)g_agg)[idx] = z;
    if (blockIdx.x == 0 && threadIdx.x < DIM) {
        g_colsum[threadIdx.x]   = 0.0f;
        g_colsumsq[threadIdx.x] = 0.0f;
    }
}

// ---------------------------------------------------------------------------
// K1: edge scatter — one warp per edge, red.global.add.v4.f32 (R3-proven)
// ---------------------------------------------------------------------------
__global__ void k1_scatter(const float* __restrict__ x,
                           const int* __restrict__ ei) {
    int warp = (blockIdx.x * blockDim.x + threadIdx.x) >> 5;
    int lane = threadIdx.x & 31;
    if (warp >= N_EDGES) return;
    int src = __ldg(&ei[warp]);
    int dst = __ldg(&ei[N_EDGES + warp]);
    float4 v = __ldg((const float4*)x + src * (DIM / 4) + lane);
    float* dp = g_agg + (size_t)dst * DIM + lane * 4;
    asm volatile("red.global.add.v4.f32 [%0], {%1, %2, %3, %4};"
                 :: "l"(dp), "f"(v.x), "f"(v.y), "f"(v.z), "f"(v.w)
                 : "memory");
}

// ---------------------------------------------------------------------------
// K2: h = ((1+eps)x + agg) @ W^T, fused per-column sum/sumsq for BN.
//     Bias omitted (cancels exactly inside BatchNorm).
//     CTA: 256 thr, tile 64 rows x 128 cols, K chunked by 32.
//     Warp grid 2x4 (32-row x 32-col warp tiles); lane grid 8x4;
//     micro-tile 4 rows x 8 cols. Conflict-free main-loop smem reads.
// ---------------------------------------------------------------------------
__global__ void __launch_bounds__(256, 3)
k2_gemm(const float* __restrict__ x, const float* __restrict__ Wm,
        const float* __restrict__ gin_eps) {
    __shared__ float As[KC][AST];     // As[k][r]
    __shared__ float Ws[KC][WST];     // Ws[k][n]
    __shared__ float cs[DIM], cs2[DIM];

    const int tid  = threadIdx.x;
    const int row0 = blockIdx.x * 64;             // 625 * 64 == 40000 exactly
    const float ce = 1.0f + __ldg(gin_eps);

    const int wid  = tid >> 5, lane = tid & 31;
    const int wr   = wid & 1,  wc   = wid >> 1;   // warp 2x4
    const int lr   = lane & 7, lc   = lane >> 3;  // lane 8x4
    const int rl   = wr * 32 + lr * 4;            // 4 contiguous rows
    const int cl   = wc * 32 + lc * 4;            // cols cl..cl+3 and cl+16..cl+19

    if (tid < DIM) { cs[tid] = 0.0f; cs2[tid] = 0.0f; }

    float acc[4][8];
#pragma unroll
    for (int q = 0; q < 4; q++)
#pragma unroll
        for (int c = 0; c < 8; c++) acc[q][c] = 0.0f;

    for (int kc = 0; kc < DIM; kc += KC) {
        __syncthreads();
        // Stage Ws[k][n] <- W[n][kc+k]  (transpose, 128 n x 8 float4)
        for (int i = tid; i < 128 * 8; i += 256) {
            int n = i >> 3, kq = i & 7;
            float4 w = __ldg((const float4*)Wm + n * 32 + (kc >> 2) + kq);
            Ws[kq * 4 + 0][n] = w.x;
            Ws[kq * 4 + 1][n] = w.y;
            Ws[kq * 4 + 2][n] = w.z;
            Ws[kq * 4 + 3][n] = w.w;
        }
        // Stage As[k][r] <- (1+eps)*x + agg  (transpose, 64 r x 8 float4)
        for (int i = tid; i < 64 * 8; i += 256) {
            int r = i >> 3, kq = i & 7;
            size_t off = (size_t)(row0 + r) * 32 + (kc >> 2) + kq;
            float4 xv = __ldg((const float4*)x + off);
            float4 gv = *((const float4*)g_agg + off);
            As[kq * 4 + 0][r] = fmaf(ce, xv.x, gv.x);
            As[kq * 4 + 1][r] = fmaf(ce, xv.y, gv.y);
            As[kq * 4 + 2][r] = fmaf(ce, xv.z, gv.z);
            As[kq * 4 + 3][r] = fmaf(ce, xv.w, gv.w);
        }
        __syncthreads();

#pragma unroll
        for (int kk = 0; kk < KC; kk++) {
            float4 av = *(const float4*)&As[kk][rl];
            float4 w0 = *(const float4*)&Ws[kk][cl];
            float4 w1 = *(const float4*)&Ws[kk][cl + 16];
            float a[4] = {av.x, av.y, av.z, av.w};
            float w[8] = {w0.x, w0.y, w0.z, w0.w, w1.x, w1.y, w1.z, w1.w};
#pragma unroll
            for (int q = 0; q < 4; q++)
#pragma unroll
                for (int c = 0; c < 8; c++)
                    acc[q][c] = fmaf(a[q], w[c], acc[q][c]);
        }
    }

    // Epilogue: store h + accumulate per-column sum/sumsq
    float csum[8], csq[8];
#pragma unroll
    for (int c = 0; c < 8; c++) { csum[c] = 0.0f; csq[c] = 0.0f; }

#pragma unroll
    for (int q = 0; q < 4; q++) {
        int row = row0 + rl + q;
        float4 o0 = {acc[q][0], acc[q][1], acc[q][2], acc[q][3]};
        float4 o1 = {acc[q][4], acc[q][5], acc[q][6], acc[q][7]};
        *(float4*)&g_h[(size_t)row * DIM + cl]      = o0;
        *(float4*)&g_h[(size_t)row * DIM + cl + 16] = o1;
#pragma unroll
        for (int c = 0; c < 8; c++) {
            csum[c] += acc[q][c];
            csq[c]  += acc[q][c] * acc[q][c];
        }
    }
#pragma unroll
    for (int c = 0; c < 4; c++) {
        atomicAdd(&cs[cl + c],       csum[c]);
        atomicAdd(&cs[cl + 16 + c],  csum[c + 4]);
        atomicAdd(&cs2[cl + c],      csq[c]);
        atomicAdd(&cs2[cl + 16 + c], csq[c + 4]);
    }
    __syncthreads();
    if (tid < DIM) {
        atomicAdd(&g_colsum[tid],   cs[tid]);
        atomicAdd(&g_colsumsq[tid], cs2[tid]);
    }
}

// ---------------------------------------------------------------------------
// K3: out = relu(gamma*(h-mean)*rsqrt(var+eps)+beta) + x
// ---------------------------------------------------------------------------
__global__ void k3_final(const float* __restrict__ x,
                         const float* __restrict__ gamma,
                         const float* __restrict__ beta,
                         float* __restrict__ out) {
    __shared__ float sc_s[DIM], sh_s[DIM];
    if (threadIdx.x < DIM) {
        int c = threadIdx.x;
        const float invN = 1.0f / (float)N_NODES;
        float mean = g_colsum[c] * invN;
        float var  = g_colsumsq[c] * invN - mean * mean;
        float inv  = rsqrtf(var + 1e-5f);
        float sc   = __ldg(&gamma[c]) * inv;
        sc_s[c] = sc;
        sh_s[c] = __ldg(&beta[c]) - mean * sc;
    }
    __syncthreads();
    const int total = N_NODES * DIM / 4;
    for (int idx = blockIdx.x * blockDim.x + threadIdx.x; idx < total;
         idx += gridDim.x * blockDim.x) {
        int c4 = (idx & 31) << 2;
        float4 h  = ((const float4*)g_h)[idx];
        float4 xv = __ldg((const float4*)x + idx);
        float4 sc = *(float4*)&sc_s[c4];
        float4 sh = *(float4*)&sh_s[c4];
        float4 o;
        o.x = fmaxf(fmaf(h.x, sc.x, sh.x), 0.0f) + xv.x;
        o.y = fmaxf(fmaf(h.y, sc.y, sh.y), 0.0f) + xv.y;
        o.z = fmaxf(fmaf(h.z, sc.z, sh.z), 0.0f) + xv.z;
        o.w = fmaxf(fmaf(h.w, sc.w, sh.w), 0.0f) + xv.w;
        ((float4*)out)[idx] = o;
    }
}

// ---------------------------------------------------------------------------
extern "C" void kernel_launch(void* const* d_in, const int* in_sizes, int n_in,
                              void* d_out, int out_size) {
    const float* x       = (const float*)d_in[0];
    const int*   ei      = (const int*)d_in[1];
    const float* Wm      = (const float*)d_in[2];
    // d_in[3] = bias: cancels exactly inside BatchNorm -> unused
    const float* gamma   = (const float*)d_in[4];
    const float* beta    = (const float*)d_in[5];
    const float* gin_eps = (const float*)d_in[6];
    float* out = (float*)d_out;

    k0z<<<1184, 256>>>();
    k1_scatter<<<N_EDGES / 8, 256>>>(x, ei);      // 1 warp per edge
    k2_gemm<<<N_NODES / 64, 256>>>(x, Wm, gin_eps);
    k3_final<<<1184, 256>>>(x, gamma, beta, out);
}